// round 12
// baseline (speedup 1.0000x reference)
#include <cuda_runtime.h>

#define SS   128
#define TT   2048
#define BB   64
#define NBLK 256              // TT / 8
#define NTHR 512
#define LOG2E 1.4426950408889634f
#define LN2F  0.6931471805599453f

typedef unsigned long long ull;

// Static parameter transforms (shared across batches).
__device__ float g_expA[SS * SS];  // e^{A[i][j]}, [i][j]
__device__ float g_expD[SS * SS];  // e^{D[j][d-1]}, [d-1][j] (transposed)
__device__ float g_vpi[SS];        // e^{pi_j}

__device__ __forceinline__ float ex2f(float x) {
    float y; asm("ex2.approx.ftz.f32 %0, %1;" : "=f"(y) : "f"(x)); return y;
}
__device__ __forceinline__ float lg2f(float x) {
    float y; asm("lg2.approx.ftz.f32 %0, %1;" : "=f"(y) : "f"(x)); return y;
}
__device__ __forceinline__ ull packf2(float lo, float hi) {
    ull u; asm("mov.b64 %0, {%1, %2};" : "=l"(u) : "f"(lo), "f"(hi)); return u;
}
__device__ __forceinline__ void unpackf2(ull u, float& lo, float& hi) {
    asm("mov.b64 {%0, %1}, %2;" : "=f"(lo), "=f"(hi) : "l"(u));
}
__device__ __forceinline__ void ffma2(ull& d, ull a, ull b) {
    asm("fma.rn.f32x2 %0, %1, %2, %0;" : "+l"(d) : "l"(a), "l"(b));
}

__global__ void hsmm_precompute(const float* __restrict__ A,
                                const float* __restrict__ D,
                                const float* __restrict__ pi) {
    int r = blockIdx.x;   // 0..127
    int j = threadIdx.x;  // 0..127
    g_expA[r * SS + j] = expf(A[r * SS + j]);
    g_expD[r * SS + j] = expf(D[j * SS + r]);   // transpose; row r = duration r+1
    if (r == 0) g_vpi[j] = expf(pi[j]);
}

// Smem layout (floats):
#define OFF_RING 0        // ring[128][128]          16384
#define OFF_PSD  16384    // psd[2][128] (double-buffered psh)
#define OFF_DF   16640    // dfar[2][4][8][128]       8192
#define OFF_PM   24832    // pmax[4][128]              512
#define OFF_RS   25344    // rs[128]
#define OFF_WR   25472    // wred[8]
#define OFF_EDS  25480    // eDs[16][128]             2048
#define SMEM_FLOATS 27528
#define SMEM_BYTES  (SMEM_FLOATS * 4)

__global__ __launch_bounds__(NTHR, 1)
void hsmm_kernel(const float* __restrict__ logB, float* __restrict__ out) {
    extern __shared__ float sm[];
    float* ring = sm + OFF_RING;
    float* psd  = sm + OFF_PSD;     // psd[buf*128 + j]
    float* dfar = sm + OFF_DF;
    float* pmax = sm + OFF_PM;
    float* rs   = sm + OFF_RS;
    float* wred = sm + OFF_WR;
    float* eDs  = sm + OFF_EDS;

    const int tid  = threadIdx.x;
    const int jr   = tid & 127;       // generic column index (init/rescale)
    const int lane = tid & 31;
    const int wrp  = tid >> 5;

    // Roles: Y pairs (tid<256): state js = tid>>1, half h = tid&1 (adjacent lanes).
    //        conv (tid>=256): deep duration sums, unchanged.
    const bool isY = (tid < 256);
    const int  js  = tid >> 1;
    const int  h   = tid & 1;

    // Init shared.
    for (int k = tid; k < 16384; k += NTHR) ring[k] = 0.0f;
    for (int k = tid; k < 8192;  k += NTHR) dfar[k] = 0.0f;
    for (int k = tid; k < 2048;  k += NTHR) eDs[k]  = g_expD[k];
    if (tid < 256) psd[tid] = 0.0f;

    // Role-specific register banks.
    ull P[32];
    int cp = 0, cb = 0;
    if (isY) {
        const int i0 = 64 * h;
#pragma unroll
        for (int k = 0; k < 32; ++k)
            P[k] = packf2(g_expA[(i0 + 2 * k) * SS + js],
                          g_expA[(i0 + 2 * k + 1) * SS + js]);
    } else {
        cp = (tid - 256) & 63; cb = (tid - 256) >> 6;
        int d0 = 17 + 28 * cb;
#pragma unroll
        for (int q = 0; q < 28; ++q)
            P[q] = *(const ull*)&g_expD[(d0 + q - 1) * SS + 2 * cp];
    }

    const float* lbp = logB + (size_t)blockIdx.x * TT * SS + js;

    // Y per-state state (both pair threads maintain identical copies).
    float vh[15];
#pragma unroll
    for (int k = 0; k < 15; ++k) vh[k] = 0.0f;
    float w = 1.0f, rw = 1.0f;
    float frw_f = 1.0f, fw_f = 1.0f, fw_pend = 1.0f;
    float Cacc = 0.0f, lb0 = 0.0f, lb1 = 0.0f, eD1j = 0.0f, vpi = 0.0f;
    float p_last = 0.0f;
    if (isY) {
        lb0 = lbp[0];
        lb1 = lbp[SS];
        rw  = ex2f(lb0 * LOG2E);
        eD1j = g_expD[js];
        vpi  = g_vpi[js];
    }

    for (int kb = 0; kb < NBLK; ++kb) {
        asm volatile("bar.sync 0;" ::: "memory");   // block entry: ring/dfar visible
        float fcor = 1.0f;
        const bool resc = (kb > 0) && ((kb & 3) == 0);
        if (resc) {
            {
                const int cq = tid >> 7;
                float mxr = 0.0f;
#pragma unroll 4
                for (int s = 0; s < 32; ++s)
                    mxr = fmaxf(mxr, ring[(32 * cq + s) * SS + jr]);
                pmax[cq * SS + jr] = mxr;
            }
            asm volatile("bar.sync 0;" ::: "memory");
            if (isY) {
                float mv = fmaxf(fmaxf(pmax[js], pmax[SS + js]),
                                 fmaxf(pmax[2 * SS + js], pmax[3 * SS + js]));
                int e = 0;
                if (mv > 0.0f) e = (__float_as_int(mv) >> 23) - 127;
                float rsv  = __int_as_float((127 - e) << 23);   // 2^{-e} exact
                float rsiv = __int_as_float((127 + e) << 23);   // 2^{+e} exact
                if (h == 0) rs[js] = rsv;
                w  *= rsv;
                rw *= rsiv;
#pragma unroll
                for (int k = 0; k < 15; ++k) vh[k] *= rsv;
                fcor = rsv;            // deep sums were computed pre-rescale
            }
            asm volatile("bar.sync 0;" ::: "memory");
            {
                const int cq = tid >> 7;
                float f = rs[jr];
#pragma unroll 4
                for (int s = 0; s < 32; ++s)
                    ring[(32 * cq + s) * SS + jr] *= f;
            }
            asm volatile("bar.sync 0;" ::: "memory");
        }

        if (isY) {
            // Preload this block's deep sums (written by conv last block).
            float deepR[8];
            {
                const int buf = kb & 1;
#pragma unroll
                for (int tau = 0; tau < 8; ++tau) {
                    const float* dfb = dfar + ((buf * 4) * 8 + tau) * SS + js;
                    deepR[tau] = ((dfb[0] + dfb[8 * SS]) +
                                  (dfb[16 * SS] + dfb[24 * SS])) * fcor;
                }
            }
#pragma unroll
            for (int tau = 0; tau < 8; ++tau) {
                const int t = 8 * kb + tau;

                // ---- off-chain pre-work (independent of this step's psh) ----
                float lbn = lbp[(size_t)min(t + 2, TT - 1) * SS];
                float e2v = ex2f(lb1 * LOG2E);     // 2^{lb_{t+1}} for rw
                float ebv = ex2f(-lb0 * LOG2E);    // 2^{-lb_t}   for w

                float nd = vh[0] * eDs[SS + js];   // d = 2
#pragma unroll
                for (int d = 3; d <= 16; ++d)
                    nd = fmaf(vh[d - 2], eDs[(d - 1) * SS + js], nd);
                nd += deepR[tau];

                // ---- matvec half: i in [64h, 64h+64) from psd[t&1] ----
                const float4* p4 = (const float4*)(psd + (t & 1) * 128) + 16 * h;
                ull a0 = 0ull, a1 = 0ull, a2 = 0ull, a3 = 0ull;
#pragma unroll
                for (int kk = 0; kk < 16; kk += 2) {
                    float4 u  = p4[kk];
                    float4 v2 = p4[kk + 1];
                    ffma2(a0, packf2(u.x,  u.y),  P[2 * kk]);
                    ffma2(a1, packf2(u.z,  u.w),  P[2 * kk + 1]);
                    ffma2(a2, packf2(v2.x, v2.y), P[2 * kk + 2]);
                    ffma2(a3, packf2(v2.z, v2.w), P[2 * kk + 3]);
                }
                float x0, x1, x2, x3, x4, x5, x6, x7;
                unpackf2(a0, x0, x1); unpackf2(a1, x2, x3);
                unpackf2(a2, x4, x5); unpackf2(a3, x6, x7);
                float half_ts = ((x0 + x1) + (x2 + x3)) + ((x4 + x5) + (x6 + x7));

                // combine halves within the lane pair — no barrier, no smem
                float ts = half_ts + __shfl_xor_sync(0xffffffffu, half_ts, 1);

                float v = ts * w;
                if (kb == 0 && tau == 0) v = vpi;
                if (h == 0) ring[(t & 127) * SS + js] = v;

                float dot = fmaf(v, eD1j, nd);
                float p = dot * rw;
                if (h == 0) psd[((t + 1) & 1) * 128 + js] = p;
                p_last = p;

                // history shift (register renaming under full unroll)
#pragma unroll
                for (int k = 14; k > 0; --k) vh[k] = vh[k - 1];
                vh[0] = v;

                // psh renorm every 16 steps (exact power-of-2 factors)
                if (tau == 7 && (kb & 1) == 1 && kb != NBLK - 1) {
                    unsigned um = __reduce_max_sync(0xffffffffu,
                                                    __float_as_uint(p));
                    if (lane == 0) wred[wrp] = __uint_as_float(um);
                    asm volatile("bar.sync 2, 256;" ::: "memory");
                    float mx = fmaxf(
                        fmaxf(fmaxf(wred[0], wred[1]), fmaxf(wred[2], wred[3])),
                        fmaxf(fmaxf(wred[4], wred[5]), fmaxf(wred[6], wred[7])));
                    int de = (__float_as_int(mx) >> 23) - 127;
                    Cacc += (float)de;
                    frw_f   = __int_as_float((127 - de) << 23);  // 2^{-de}
                    fw_pend = __int_as_float((127 + de) << 23);  // 2^{+de}
                }

                rw = rw * e2v * frw_f;  frw_f = 1.0f;
                w  = w  * ebv * fw_f;   fw_f = fw_pend; fw_pend = 1.0f;
                lb0 = lb1; lb1 = lbn;

                asm volatile("bar.sync 2, 256;" ::: "memory");  // ONE bar/step
            }
        } else {
            // ---- Conv: deep duration sums (d=17..128) for block kb+1 ----
            const int t0 = 8 * (kb + 1);
            const int d0 = 17 + 28 * cb;
            const int u0 = t0 - d0 - 26;
            ull acc[8] = {0ull,0ull,0ull,0ull,0ull,0ull,0ull,0ull};
#pragma unroll
            for (int m = 0; m < 35; ++m) {
                ull v = *(const ull*)&ring[((u0 + m + 8192) & 127) * SS + 2 * cp];
#pragma unroll
                for (int tau = 0; tau < 8; ++tau) {
                    int q = tau + 27 - m;
                    if (q >= 0 && q <= 27) ffma2(acc[tau], v, P[q]);
                }
            }
            const int obuf = (kb + 1) & 1;
#pragma unroll
            for (int tau = 0; tau < 8; ++tau)
                *(ull*)&dfar[((obuf * 4 + cb) * 8 + tau) * SS + 2 * cp] = acc[tau];
        }
    }

    // loglik[b] = ln2 * (Cacc + lg2(sum_j p_j))  — even pair-threads hold p.
    asm volatile("bar.sync 0;" ::: "memory");
    if (isY) {
        float s = (h == 0) ? p_last : 0.0f;
#pragma unroll
        for (int o = 16; o; o >>= 1)
            s += __shfl_xor_sync(0xffffffffu, s, o);
        if (lane == 0) wred[wrp] = s;
        asm volatile("bar.sync 2, 256;" ::: "memory");
        if (tid == 0) {
            float tot = ((wred[0] + wred[1]) + (wred[2] + wred[3])) +
                        ((wred[4] + wred[5]) + (wred[6] + wred[7]));
            out[blockIdx.x] = (Cacc + lg2f(tot)) * LN2F;
        }
    }
}

extern "C" void kernel_launch(void* const* d_in, const int* in_sizes, int n_in,
                              void* d_out, int out_size) {
    const float* logB = (const float*)d_in[0];  // (B, T, S)
    const float* pi   = (const float*)d_in[1];  // (S,)
    const float* A    = (const float*)d_in[2];  // (S, S)
    const float* D    = (const float*)d_in[3];  // (S, DMAX)

    hsmm_precompute<<<128, 128>>>(A, D, pi);

    cudaFuncSetAttribute(hsmm_kernel,
                         cudaFuncAttributeMaxDynamicSharedMemorySize, SMEM_BYTES);
    hsmm_kernel<<<BB, NTHR, SMEM_BYTES>>>(logB, (float*)d_out);
}

// round 13
// speedup vs baseline: 1.0279x; 1.0279x over previous
#include <cuda_runtime.h>

#define SS   128
#define TT   2048
#define BB   64
#define NBLK 256              // TT / 8
#define NTHR 512
#define LOG2E 1.4426950408889634f
#define LN2F  0.6931471805599453f

typedef unsigned long long ull;

// Static parameter transforms (shared across batches).
__device__ float g_expA[SS * SS];  // e^{A[i][j]}, [i][j]
__device__ float g_expD[SS * SS];  // e^{D[j][d-1]}, [d-1][j] (transposed)
__device__ float g_vpi[SS];        // e^{pi_j}

__device__ __forceinline__ float ex2f(float x) {
    float y; asm("ex2.approx.ftz.f32 %0, %1;" : "=f"(y) : "f"(x)); return y;
}
__device__ __forceinline__ float lg2f(float x) {
    float y; asm("lg2.approx.ftz.f32 %0, %1;" : "=f"(y) : "f"(x)); return y;
}
__device__ __forceinline__ ull packf2(float lo, float hi) {
    ull u; asm("mov.b64 %0, {%1, %2};" : "=l"(u) : "f"(lo), "f"(hi)); return u;
}
__device__ __forceinline__ void unpackf2(ull u, float& lo, float& hi) {
    asm("mov.b64 {%0, %1}, %2;" : "=f"(lo), "=f"(hi) : "l"(u));
}
__device__ __forceinline__ void ffma2(ull& d, ull a, ull b) {
    asm("fma.rn.f32x2 %0, %1, %2, %0;" : "+l"(d) : "l"(a), "l"(b));
}

__global__ void hsmm_precompute(const float* __restrict__ A,
                                const float* __restrict__ D,
                                const float* __restrict__ pi) {
    int r = blockIdx.x;   // 0..127
    int j = threadIdx.x;  // 0..127
    g_expA[r * SS + j] = expf(A[r * SS + j]);
    g_expD[r * SS + j] = expf(D[j * SS + r]);   // transpose; row r = duration r+1
    if (r == 0) g_vpi[j] = expf(pi[j]);
}

// Smem layout (floats):
#define OFF_RING 0        // ring[128][128]          16384
#define OFF_PSH  16384    // psh[128]
#define OFF_TP   16512    // tp[128]
#define OFF_DF   16640    // dfar[2][4][8][128]       8192
#define OFF_PM   24832    // pmax[4][128]              512
#define OFF_RS   25344    // rs[128]
#define OFF_WR   25472    // wred[8]
#define SMEM_FLOATS 25480
#define SMEM_BYTES  (SMEM_FLOATS * 4)

__global__ __launch_bounds__(NTHR, 1)
void hsmm_kernel(const float* __restrict__ logB, float* __restrict__ out) {
    extern __shared__ float sm[];
    float* ring = sm + OFF_RING;
    float* psh  = sm + OFF_PSH;
    float* tp   = sm + OFF_TP;
    float* dfar = sm + OFF_DF;
    float* pmax = sm + OFF_PM;
    float* rs   = sm + OFF_RS;
    float* wred = sm + OFF_WR;

    const int tid  = threadIdx.x;
    const int j    = tid & 127;
    const int lane = tid & 31;
    const int wrp  = tid >> 5;
    const bool isY = (tid < 128);

    // Init shared: ring zero (0 == exp-domain -inf), dfar zero, psh zero.
    for (int k = tid; k < 16384; k += NTHR) ring[k] = 0.0f;
    for (int k = tid; k < 8192;  k += NTHR) dfar[k] = 0.0f;
    if (tid < 128) psh[tid] = 0.0f;

    // Role-specific register banks.
    ull P[32];
    int cp = 0, cb = 0;
    if (tid < 256) {
        const int i0 = isY ? 0 : 64;
#pragma unroll
        for (int k = 0; k < 32; ++k)
            P[k] = packf2(g_expA[(i0 + 2 * k) * SS + j],
                          g_expA[(i0 + 2 * k + 1) * SS + j]);
    } else {
        int g = tid - 256; cp = g & 63; cb = g >> 6;
        int d0 = 17 + 28 * cb;
#pragma unroll
        for (int q = 0; q < 28; ++q)
            P[q] = *(const ull*)&g_expD[(d0 + q - 1) * SS + 2 * cp];
    }

    const float* lbp = logB + (size_t)blockIdx.x * TT * SS + j;

    // Y state: near-dot coefficients d=1..16 in REGISTERS (static params).
    float eDreg[16];
    float vh[15];
#pragma unroll
    for (int k = 0; k < 15; ++k) vh[k] = 0.0f;
    float w = 1.0f, rw = 1.0f;
    float frw_f = 1.0f, fw_f = 1.0f, fw_pend = 1.0f;
    float Cacc = 0.0f, lb0 = 0.0f, lb1 = 0.0f, vpi = 0.0f;
    if (isY) {
#pragma unroll
        for (int d = 0; d < 16; ++d) eDreg[d] = g_expD[d * SS + j];
        lb0 = lbp[0];
        lb1 = lbp[SS];
        rw  = ex2f(lb0 * LOG2E);
        vpi = g_vpi[j];
    }

    for (int kb = 0; kb < NBLK; ++kb) {
        asm volatile("bar.sync 0;" ::: "memory");   // block entry: ring/dfar visible
        float fcor = 1.0f;
        const bool resc = (kb > 0) && ((kb & 3) == 0);
        if (resc) {
            {
                const int cq = tid >> 7;
                float mxr = 0.0f;
#pragma unroll 4
                for (int s = 0; s < 32; ++s)
                    mxr = fmaxf(mxr, ring[(32 * cq + s) * SS + j]);
                pmax[cq * SS + j] = mxr;
            }
            asm volatile("bar.sync 0;" ::: "memory");
            if (isY) {
                float mv = fmaxf(fmaxf(pmax[j], pmax[SS + j]),
                                 fmaxf(pmax[2 * SS + j], pmax[3 * SS + j]));
                int e = 0;
                if (mv > 0.0f) e = (__float_as_int(mv) >> 23) - 127;
                float rsv  = __int_as_float((127 - e) << 23);   // 2^{-e} exact
                float rsiv = __int_as_float((127 + e) << 23);   // 2^{+e} exact
                rs[j] = rsv;
                w  *= rsv;
                rw *= rsiv;
#pragma unroll
                for (int k = 0; k < 15; ++k) vh[k] *= rsv;
                fcor = rsv;            // deep sums were computed pre-rescale
            }
            asm volatile("bar.sync 0;" ::: "memory");
            {
                const int cq = tid >> 7;
                float f = rs[j];
#pragma unroll 4
                for (int s = 0; s < 32; ++s)
                    ring[(32 * cq + s) * SS + j] *= f;
            }
            asm volatile("bar.sync 0;" ::: "memory");
        }

        if (tid < 256) {
            // Y: preload this block's deep sums (computed last block by conv)
            float deepR[8];
            if (isY) {
                const int buf = kb & 1;
#pragma unroll
                for (int tau = 0; tau < 8; ++tau) {
                    const float* dfb = dfar + ((buf * 4) * 8 + tau) * SS + j;
                    deepR[tau] = ((dfb[0] + dfb[8 * SS]) +
                                  (dfb[16 * SS] + dfb[24 * SS])) * fcor;
                }
            }
#pragma unroll
            for (int tau = 0; tau < 8; ++tau) {
                const int t = 8 * kb + tau;

                // ---- X: matvec partial over own 64-state band ----
                float tsum;
                {
                    const float4* p4 = (const float4*)psh;
                    const int base = isY ? 0 : 16;
                    ull s0 = 0ull, s1 = 0ull, s2 = 0ull, s3 = 0ull;
#pragma unroll
                    for (int kk = 0; kk < 16; kk += 2) {
                        float4 v0 = p4[base + kk];
                        float4 v1 = p4[base + kk + 1];
                        ffma2(s0, packf2(v0.x, v0.y), P[2 * kk]);
                        ffma2(s1, packf2(v0.z, v0.w), P[2 * kk + 1]);
                        ffma2(s2, packf2(v1.x, v1.y), P[2 * kk + 2]);
                        ffma2(s3, packf2(v1.z, v1.w), P[2 * kk + 3]);
                    }
                    float a, b, c, d, e, f, g, h;
                    unpackf2(s0, a, b); unpackf2(s1, c, d);
                    unpackf2(s2, e, f); unpackf2(s3, g, h);
                    tsum = ((a + b) + (c + d)) + ((e + f) + (g + h));
                }
                if (!isY) tp[j] = tsum;
                asm volatile("bar.sync 2, 256;" ::: "memory");   // bar A

                // ---- Y: serial recurrence (register-only near-dot) ----
                if (isY) {
                    // off-chain: input prefetch + scale-factor ex2's
                    float lbn = lbp[(size_t)min(t + 2, TT - 1) * SS];
                    float e2v = ex2f(lb1 * LOG2E);     // 2^{lb_{t+1}} for rw
                    float ebv = ex2f(-lb0 * LOG2E);    // 2^{-lb_t}   for w

                    // chain
                    float ts = tsum + tp[j];
                    float v  = (t == 0) ? vpi : ts * w;
                    ring[(t & 127) * SS + j] = v;

                    // near dot d=1..16, all-register FMAs (4 chains)
                    float n0 = v     * eDreg[0];
                    float n1 = vh[0] * eDreg[1];
                    float n2 = vh[1] * eDreg[2];
                    float n3 = vh[2] * eDreg[3];
#pragma unroll
                    for (int d2 = 4; d2 < 16; d2 += 4) {
                        n0 = fmaf(vh[d2 - 1], eDreg[d2    ], n0);
                        n1 = fmaf(vh[d2    ], eDreg[d2 + 1], n1);
                        n2 = fmaf(vh[d2 + 1], eDreg[d2 + 2], n2);
                        n3 = fmaf(vh[d2 + 2], eDreg[d2 + 3], n3);
                    }
                    float dot = ((n0 + n1) + (n2 + n3)) + deepR[tau];
                    float p = dot * rw;
                    psh[j] = p;

                    // history shift (register renaming under full unroll)
#pragma unroll
                    for (int k = 14; k > 0; --k) vh[k] = vh[k - 1];
                    vh[0] = v;

                    // psh renorm every 16 steps (exact power-of-2 factors)
                    if (tau == 7 && (kb & 1) == 1 && kb != NBLK - 1) {
                        unsigned um = __reduce_max_sync(0xffffffffu,
                                                        __float_as_uint(p));
                        if (lane == 0) wred[wrp] = __uint_as_float(um);
                        asm volatile("bar.sync 1, 128;" ::: "memory");
                        float mx = fmaxf(fmaxf(wred[0], wred[1]),
                                         fmaxf(wred[2], wred[3]));
                        int de = (__float_as_int(mx) >> 23) - 127;
                        Cacc += (float)de;
                        frw_f   = __int_as_float((127 - de) << 23);  // 2^{-de}
                        fw_pend = __int_as_float((127 + de) << 23);  // 2^{+de}
                    }

                    // end-of-step scale updates (off the next step's chain)
                    rw = rw * e2v * frw_f;  frw_f = 1.0f;
                    w  = w  * ebv * fw_f;   fw_f = fw_pend; fw_pend = 1.0f;
                    lb0 = lb1; lb1 = lbn;
                }
                asm volatile("bar.sync 2, 256;" ::: "memory");   // bar B
            }
        } else {
            // ---- Conv: deep duration sums (d=17..128) for block kb+1 ----
            const int t0 = 8 * (kb + 1);
            const int d0 = 17 + 28 * cb;
            const int u0 = t0 - d0 - 26;
            ull acc[8] = {0ull,0ull,0ull,0ull,0ull,0ull,0ull,0ull};
#pragma unroll
            for (int m = 0; m < 35; ++m) {
                ull v = *(const ull*)&ring[((u0 + m + 8192) & 127) * SS + 2 * cp];
#pragma unroll
                for (int tau = 0; tau < 8; ++tau) {
                    int q = tau + 27 - m;
                    if (q >= 0 && q <= 27) ffma2(acc[tau], v, P[q]);
                }
            }
            const int obuf = (kb + 1) & 1;
#pragma unroll
            for (int tau = 0; tau < 8; ++tau)
                *(ull*)&dfar[((obuf * 4 + cb) * 8 + tau) * SS + 2 * cp] = acc[tau];
        }
    }

    // loglik[b] = ln2 * (Cacc + lg2(sum_j psh_j))
    asm volatile("bar.sync 0;" ::: "memory");
    if (isY) {
        float s = psh[j];
#pragma unroll
        for (int o = 16; o; o >>= 1)
            s += __shfl_xor_sync(0xffffffffu, s, o);
        if (lane == 0) wred[wrp] = s;
        asm volatile("bar.sync 1, 128;" ::: "memory");
        if (tid == 0) {
            float tot = (wred[0] + wred[1]) + (wred[2] + wred[3]);
            out[blockIdx.x] = (Cacc + lg2f(tot)) * LN2F;
        }
    }
}

extern "C" void kernel_launch(void* const* d_in, const int* in_sizes, int n_in,
                              void* d_out, int out_size) {
    const float* logB = (const float*)d_in[0];  // (B, T, S)
    const float* pi   = (const float*)d_in[1];  // (S,)
    const float* A    = (const float*)d_in[2];  // (S, S)
    const float* D    = (const float*)d_in[3];  // (S, DMAX)

    hsmm_precompute<<<128, 128>>>(A, D, pi);

    cudaFuncSetAttribute(hsmm_kernel,
                         cudaFuncAttributeMaxDynamicSharedMemorySize, SMEM_BYTES);
    hsmm_kernel<<<BB, NTHR, SMEM_BYTES>>>(logB, (float*)d_out);
}

// round 14
// speedup vs baseline: 1.0613x; 1.0326x over previous
#include <cuda_runtime.h>

#define SS   128
#define TT   2048
#define BB   64
#define NBLK 256              // TT / 8
#define NTHR 512
#define LOG2E 1.4426950408889634f
#define LN2F  0.6931471805599453f

typedef unsigned long long ull;

// Static parameter transforms (shared across batches).
__device__ float g_expA[SS * SS];  // e^{A[i][j]}, [i][j]
__device__ float g_expD[SS * SS];  // e^{D[j][d-1]}, [d-1][j] (transposed)
__device__ float g_vpi[SS];        // e^{pi_j}

__device__ __forceinline__ float ex2f(float x) {
    float y; asm("ex2.approx.ftz.f32 %0, %1;" : "=f"(y) : "f"(x)); return y;
}
__device__ __forceinline__ float lg2f(float x) {
    float y; asm("lg2.approx.ftz.f32 %0, %1;" : "=f"(y) : "f"(x)); return y;
}
__device__ __forceinline__ ull packf2(float lo, float hi) {
    ull u; asm("mov.b64 %0, {%1, %2};" : "=l"(u) : "f"(lo), "f"(hi)); return u;
}
__device__ __forceinline__ void unpackf2(ull u, float& lo, float& hi) {
    asm("mov.b64 {%0, %1}, %2;" : "=f"(lo), "=f"(hi) : "l"(u));
}
__device__ __forceinline__ void ffma2(ull& d, ull a, ull b) {
    asm("fma.rn.f32x2 %0, %1, %2, %0;" : "+l"(d) : "l"(a), "l"(b));
}

__global__ void hsmm_precompute(const float* __restrict__ A,
                                const float* __restrict__ D,
                                const float* __restrict__ pi) {
    int r = blockIdx.x;   // 0..127
    int j = threadIdx.x;  // 0..127
    g_expA[r * SS + j] = expf(A[r * SS + j]);
    g_expD[r * SS + j] = expf(D[j * SS + r]);   // transpose; row r = duration r+1
    if (r == 0) g_vpi[j] = expf(pi[j]);
}

// Smem layout (floats):
#define OFF_RING 0        // ring[128][128]          16384
#define OFF_PSH  16384    // psh[128]
#define OFF_TP   16512    // tp[128]
#define OFF_DF   16640    // dfar[2][4][8][128]       8192
#define OFF_PM   24832    // pmax[4][128]              512
#define OFF_RS   25344    // rs[128]
#define OFF_WR   25472    // wred[8]
#define SMEM_FLOATS 25480
#define SMEM_BYTES  (SMEM_FLOATS * 4)

__global__ __launch_bounds__(NTHR, 1)
void hsmm_kernel(const float* __restrict__ logB, float* __restrict__ out) {
    extern __shared__ float sm[];
    float* ring = sm + OFF_RING;
    float* psh  = sm + OFF_PSH;
    float* tp   = sm + OFF_TP;
    float* dfar = sm + OFF_DF;
    float* pmax = sm + OFF_PM;
    float* rs   = sm + OFF_RS;
    float* wred = sm + OFF_WR;

    const int tid  = threadIdx.x;
    const int j    = tid & 127;
    const int lane = tid & 31;
    const int wrp  = tid >> 5;
    const bool isY = (tid < 128);

    // Init shared: ring zero (0 == exp-domain -inf), dfar zero, psh zero.
    for (int k = tid; k < 16384; k += NTHR) ring[k] = 0.0f;
    for (int k = tid; k < 8192;  k += NTHR) dfar[k] = 0.0f;
    if (tid < 128) psh[tid] = 0.0f;

    // Role-specific register banks.
    ull P[32];
    int cp = 0, cb = 0;
    if (tid < 256) {
        const int i0 = isY ? 0 : 64;
#pragma unroll
        for (int k = 0; k < 32; ++k)
            P[k] = packf2(g_expA[(i0 + 2 * k) * SS + j],
                          g_expA[(i0 + 2 * k + 1) * SS + j]);
    } else {
        int g = tid - 256; cp = g & 63; cb = g >> 6;
        int d0 = 17 + 28 * cb;
#pragma unroll
        for (int q = 0; q < 28; ++q)
            P[q] = *(const ull*)&g_expD[(d0 + q - 1) * SS + 2 * cp];
    }

    const float* lbp = logB + (size_t)blockIdx.x * TT * SS + j;

    // Y state: near-dot coefficients d=1..16 in registers (static params).
    float eDreg[16];
    float vh[15];
#pragma unroll
    for (int k = 0; k < 15; ++k) vh[k] = 0.0f;
    float w = 1.0f, rw = 1.0f;
    float frw_f = 1.0f, fw_f = 1.0f, fw_pend = 1.0f;
    float Cacc = 0.0f, lb0 = 0.0f, lb1 = 0.0f, vpi = 0.0f;
    if (isY) {
#pragma unroll
        for (int d = 0; d < 16; ++d) eDreg[d] = g_expD[d * SS + j];
        lb0 = lbp[0];
        lb1 = lbp[SS];
        rw  = ex2f(lb0 * LOG2E);
        vpi = g_vpi[j];
    }

    for (int kb = 0; kb < NBLK; ++kb) {
        asm volatile("bar.sync 0;" ::: "memory");   // block entry: ring/dfar visible
        float fcor = 1.0f;
        const bool resc = (kb > 0) && ((kb & 3) == 0);
        if (resc) {
            {
                const int cq = tid >> 7;
                float mxr = 0.0f;
#pragma unroll 4
                for (int s = 0; s < 32; ++s)
                    mxr = fmaxf(mxr, ring[(32 * cq + s) * SS + j]);
                pmax[cq * SS + j] = mxr;
            }
            asm volatile("bar.sync 0;" ::: "memory");
            if (isY) {
                float mv = fmaxf(fmaxf(pmax[j], pmax[SS + j]),
                                 fmaxf(pmax[2 * SS + j], pmax[3 * SS + j]));
                int e = 0;
                if (mv > 0.0f) e = (__float_as_int(mv) >> 23) - 127;
                float rsv  = __int_as_float((127 - e) << 23);   // 2^{-e} exact
                float rsiv = __int_as_float((127 + e) << 23);   // 2^{+e} exact
                rs[j] = rsv;
                w  *= rsv;
                rw *= rsiv;
#pragma unroll
                for (int k = 0; k < 15; ++k) vh[k] *= rsv;
                fcor = rsv;            // deep sums were computed pre-rescale
            }
            asm volatile("bar.sync 0;" ::: "memory");
            {
                const int cq = tid >> 7;
                float f = rs[j];
#pragma unroll 4
                for (int s = 0; s < 32; ++s)
                    ring[(32 * cq + s) * SS + j] *= f;
            }
            asm volatile("bar.sync 0;" ::: "memory");
        }

        if (tid < 256) {
            if (isY) {
                // ---- Y producer/consumer pipeline ----
                float deepR[8];
                {
                    const int buf = kb & 1;
#pragma unroll
                    for (int tau = 0; tau < 8; ++tau) {
                        const float* dfb = dfar + ((buf * 4) * 8 + tau) * SS + j;
                        deepR[tau] = ((dfb[0] + dfb[8 * SS]) +
                                      (dfb[16 * SS] + dfb[24 * SS])) * fcor;
                    }
                }
#pragma unroll
                for (int tau = 0; tau < 8; ++tau) {
                    const int t = 8 * kb + tau;

                    // signal helpers: psh_{t-1} is ready (non-blocking)
                    asm volatile("bar.arrive 3, 256;" ::: "memory");
                    // Y-internal: make all psh_{t-1} writes visible to Y reads
                    asm volatile("bar.sync 1, 128;" ::: "memory");

                    // own matvec half: i in [0,64)
                    float tsum;
                    {
                        const float4* p4 = (const float4*)psh;
                        ull s0 = 0ull, s1 = 0ull, s2 = 0ull, s3 = 0ull;
#pragma unroll
                        for (int kk = 0; kk < 16; kk += 2) {
                            float4 v0 = p4[kk];
                            float4 v1 = p4[kk + 1];
                            ffma2(s0, packf2(v0.x, v0.y), P[2 * kk]);
                            ffma2(s1, packf2(v0.z, v0.w), P[2 * kk + 1]);
                            ffma2(s2, packf2(v1.x, v1.y), P[2 * kk + 2]);
                            ffma2(s3, packf2(v1.z, v1.w), P[2 * kk + 3]);
                        }
                        float a, b, c, d, e, f, g, h;
                        unpackf2(s0, a, b); unpackf2(s1, c, d);
                        unpackf2(s2, e, f); unpackf2(s3, g, h);
                        tsum = ((a + b) + (c + d)) + ((e + f) + (g + h));
                    }

                    // off-chain pre-work, overlapped with helper round-trip
                    float lbn = lbp[(size_t)min(t + 2, TT - 1) * SS];
                    float e2v = ex2f(lb1 * LOG2E);     // 2^{lb_{t+1}} for rw
                    float ebv = ex2f(-lb0 * LOG2E);    // 2^{-lb_t}   for w

                    float nd = vh[0] * eDreg[1];       // near dot d=2..16 (regs)
                    float n2 = vh[1] * eDreg[2];
                    float n3 = vh[2] * eDreg[3];
#pragma unroll
                    for (int d2 = 4; d2 < 16; d2 += 3) {
                        nd = fmaf(vh[d2 - 1], eDreg[d2], nd);
                        if (d2 + 1 < 16) n2 = fmaf(vh[d2], eDreg[d2 + 1], n2);
                        if (d2 + 2 < 16) n3 = fmaf(vh[d2 + 1], eDreg[d2 + 2], n3);
                    }
                    float ndt = (nd + n2) + (n3 + deepR[tau]);

                    // wait for helpers' tp_t
                    asm volatile("bar.sync 4, 256;" ::: "memory");

                    float ts = tsum + tp[j];
                    float v  = (t == 0) ? vpi : ts * w;
                    ring[(t & 127) * SS + j] = v;

                    float dot = fmaf(v, eDreg[0], ndt);
                    float p = dot * rw;
                    psh[j] = p;

                    // history shift (register renaming under full unroll)
#pragma unroll
                    for (int k = 14; k > 0; --k) vh[k] = vh[k - 1];
                    vh[0] = v;

                    // psh renorm every 16 steps (exact power-of-2 factors)
                    if (tau == 7 && (kb & 1) == 1 && kb != NBLK - 1) {
                        unsigned um = __reduce_max_sync(0xffffffffu,
                                                        __float_as_uint(p));
                        if (lane == 0) wred[wrp] = __uint_as_float(um);
                        asm volatile("bar.sync 1, 128;" ::: "memory");
                        float mx = fmaxf(fmaxf(wred[0], wred[1]),
                                         fmaxf(wred[2], wred[3]));
                        int de = (__float_as_int(mx) >> 23) - 127;
                        Cacc += (float)de;
                        frw_f   = __int_as_float((127 - de) << 23);  // 2^{-de}
                        fw_pend = __int_as_float((127 + de) << 23);  // 2^{+de}
                    }

                    rw = rw * e2v * frw_f;  frw_f = 1.0f;
                    w  = w  * ebv * fw_f;   fw_f = fw_pend; fw_pend = 1.0f;
                    lb0 = lb1; lb1 = lbn;
                }
            } else {
                // ---- Helper: matvec half i in [64,128), producer of tp ----
#pragma unroll
                for (int tau = 0; tau < 8; ++tau) {
                    asm volatile("bar.sync 3, 256;" ::: "memory");  // psh ready
                    float tsum;
                    {
                        const float4* p4 = (const float4*)psh;
                        ull s0 = 0ull, s1 = 0ull, s2 = 0ull, s3 = 0ull;
#pragma unroll
                        for (int kk = 0; kk < 16; kk += 2) {
                            float4 v0 = p4[16 + kk];
                            float4 v1 = p4[16 + kk + 1];
                            ffma2(s0, packf2(v0.x, v0.y), P[2 * kk]);
                            ffma2(s1, packf2(v0.z, v0.w), P[2 * kk + 1]);
                            ffma2(s2, packf2(v1.x, v1.y), P[2 * kk + 2]);
                            ffma2(s3, packf2(v1.z, v1.w), P[2 * kk + 3]);
                        }
                        float a, b, c, d, e, f, g, h;
                        unpackf2(s0, a, b); unpackf2(s1, c, d);
                        unpackf2(s2, e, f); unpackf2(s3, g, h);
                        tsum = ((a + b) + (c + d)) + ((e + f) + (g + h));
                    }
                    tp[j] = tsum;
                    asm volatile("bar.arrive 4, 256;" ::: "memory"); // tp ready
                }
            }
        } else {
            // ---- Conv: deep duration sums (d=17..128) for block kb+1 ----
            const int t0 = 8 * (kb + 1);
            const int d0 = 17 + 28 * cb;
            const int u0 = t0 - d0 - 26;
            ull acc[8] = {0ull,0ull,0ull,0ull,0ull,0ull,0ull,0ull};
#pragma unroll
            for (int m = 0; m < 35; ++m) {
                ull v = *(const ull*)&ring[((u0 + m + 8192) & 127) * SS + 2 * cp];
#pragma unroll
                for (int tau = 0; tau < 8; ++tau) {
                    int q = tau + 27 - m;
                    if (q >= 0 && q <= 27) ffma2(acc[tau], v, P[q]);
                }
            }
            const int obuf = (kb + 1) & 1;
#pragma unroll
            for (int tau = 0; tau < 8; ++tau)
                *(ull*)&dfar[((obuf * 4 + cb) * 8 + tau) * SS + 2 * cp] = acc[tau];
        }
    }

    // loglik[b] = ln2 * (Cacc + lg2(sum_j psh_j))
    asm volatile("bar.sync 0;" ::: "memory");
    if (isY) {
        float s = psh[j];
#pragma unroll
        for (int o = 16; o; o >>= 1)
            s += __shfl_xor_sync(0xffffffffu, s, o);
        if (lane == 0) wred[wrp] = s;
        asm volatile("bar.sync 1, 128;" ::: "memory");
        if (tid == 0) {
            float tot = (wred[0] + wred[1]) + (wred[2] + wred[3]);
            out[blockIdx.x] = (Cacc + lg2f(tot)) * LN2F;
        }
    }
}

extern "C" void kernel_launch(void* const* d_in, const int* in_sizes, int n_in,
                              void* d_out, int out_size) {
    const float* logB = (const float*)d_in[0];  // (B, T, S)
    const float* pi   = (const float*)d_in[1];  // (S,)
    const float* A    = (const float*)d_in[2];  // (S, S)
    const float* D    = (const float*)d_in[3];  // (S, DMAX)

    hsmm_precompute<<<128, 128>>>(A, D, pi);

    cudaFuncSetAttribute(hsmm_kernel,
                         cudaFuncAttributeMaxDynamicSharedMemorySize, SMEM_BYTES);
    hsmm_kernel<<<BB, NTHR, SMEM_BYTES>>>(logB, (float*)d_out);
}

// round 16
// speedup vs baseline: 1.3240x; 1.2475x over previous
#include <cuda_runtime.h>
#include <cstdint>

#define SS   128
#define TT   2048
#define BB   64
#define NBLK 256              // TT / 8
#define NTHR 256
#define LOG2E 1.4426950408889634f
#define LN2F  0.6931471805599453f

typedef unsigned long long ull;

// Static parameter transforms (shared across batches).
__device__ float g_expA[SS * SS];  // e^{A[i][j]}, [i][j]
__device__ float g_expD[SS * SS];  // e^{D[j][d-1]}, [d-1][j] (transposed)
__device__ float g_vpi[SS];        // e^{pi_j}

__device__ __forceinline__ float ex2f(float x) {
    float y; asm("ex2.approx.ftz.f32 %0, %1;" : "=f"(y) : "f"(x)); return y;
}
__device__ __forceinline__ float lg2f(float x) {
    float y; asm("lg2.approx.ftz.f32 %0, %1;" : "=f"(y) : "f"(x)); return y;
}
__device__ __forceinline__ ull packf2(float lo, float hi) {
    ull u; asm("mov.b64 %0, {%1, %2};" : "=l"(u) : "f"(lo), "f"(hi)); return u;
}
__device__ __forceinline__ void unpackf2(ull u, float& lo, float& hi) {
    asm("mov.b64 {%0, %1}, %2;" : "=f"(lo), "=f"(hi) : "l"(u));
}
__device__ __forceinline__ void ffma2(ull& d, ull a, ull b) {
    asm("fma.rn.f32x2 %0, %1, %2, %0;" : "+l"(d) : "l"(a), "l"(b));
}
__device__ __forceinline__ unsigned smem_u32(const void* p) {
    unsigned a;
    asm("{ .reg .u64 t; cvta.to.shared.u64 t, %1; cvt.u32.u64 %0, t; }"
        : "=r"(a) : "l"(p));
    return a;
}
__device__ __forceinline__ unsigned mapa1(unsigned a, unsigned rank) {
    unsigned r;
    asm("mapa.shared::cluster.u32 %0, %1, %2;" : "=r"(r) : "r"(a), "r"(rank));
    return r;
}
__device__ __forceinline__ void st_rm_f32(unsigned a, float v) {
    asm volatile("st.shared::cluster.b32 [%0], %1;"
                 :: "r"(a), "r"(__float_as_uint(v)) : "memory");
}
__device__ __forceinline__ void st_rm_u64(unsigned a, ull v) {
    asm volatile("st.shared::cluster.b64 [%0], %1;" :: "r"(a), "l"(v) : "memory");
}
#define CARRIVE() asm volatile("barrier.cluster.arrive.aligned;" ::: "memory")
#define CWAIT()   asm volatile("barrier.cluster.wait.aligned;"   ::: "memory")

__global__ void hsmm_precompute(const float* __restrict__ A,
                                const float* __restrict__ D,
                                const float* __restrict__ pi) {
    int r = blockIdx.x;   // 0..127
    int j = threadIdx.x;  // 0..127
    g_expA[r * SS + j] = expf(A[r * SS + j]);
    g_expD[r * SS + j] = expf(D[j * SS + r]);   // transpose; row r = duration r+1
    if (r == 0) g_vpi[j] = expf(pi[j]);
}

// Smem layout (floats) — identical in both ranks (rank1 uses ring/rs only):
#define OFF_RING 0        // ring[128][128]          16384
#define OFF_PSH  16384    // psh[128]
#define OFF_TP   16512    // tp[128]
#define OFF_DF   16640    // dfar[2][4][8][128]       8192
#define OFF_PM   24832    // pmax[2][128]              256
#define OFF_RS   25088    // rs[128]
#define OFF_WR   25216    // wred[8]
#define SMEM_FLOATS 25224
#define SMEM_BYTES  (SMEM_FLOATS * 4)

__global__ void __launch_bounds__(NTHR, 1) __cluster_dims__(2, 1, 1)
hsmm_kernel(const float* __restrict__ logB, float* __restrict__ out) {
    extern __shared__ float sm[];
    float* ring = sm + OFF_RING;
    float* psh  = sm + OFF_PSH;
    float* tp   = sm + OFF_TP;
    float* dfar = sm + OFF_DF;
    float* pmax = sm + OFF_PM;
    float* rs   = sm + OFF_RS;
    float* wred = sm + OFF_WR;

    const int tid  = threadIdx.x;
    const int j    = tid & 127;
    const int lane = tid & 31;
    const int wrp  = tid >> 5;

    unsigned rank;
    asm("mov.u32 %0, %%cluster_ctarank;" : "=r"(rank));
    const int b = blockIdx.x >> 1;
    const bool isC = (rank == 1);           // conv CTA
    const bool isY = (!isC) && (tid < 128); // serial-chain warps in rank 0

    // Init local shared.
    for (int k = tid; k < 16384; k += NTHR) ring[k] = 0.0f;
    if (!isC) {
        for (int k = tid; k < 8192; k += NTHR) dfar[k] = 0.0f;
        if (tid < 128) psh[tid] = 0.0f;
    }

    // Role-specific register banks + remote addresses.
    ull P[32];
    int cp = 0, cb = 0;
    unsigned ring_rm = 0, rs_rm = 0, df_rm = 0;
    if (!isC) {
        const int i0 = isY ? 0 : 64;
#pragma unroll
        for (int k = 0; k < 32; ++k)
            P[k] = packf2(g_expA[(i0 + 2 * k) * SS + j],
                          g_expA[(i0 + 2 * k + 1) * SS + j]);
        if (isY) {
            ring_rm = mapa1(smem_u32(ring), 1);
            rs_rm   = mapa1(smem_u32(rs), 1);
        }
    } else {
        cp = tid & 63; cb = tid >> 6;       // state pair, duration band
        int d0 = 17 + 28 * cb;
#pragma unroll
        for (int q = 0; q < 28; ++q)
            P[q] = *(const ull*)&g_expD[(d0 + q - 1) * SS + 2 * cp];
        df_rm = mapa1(smem_u32(dfar), 0);
    }

    const float* lbp = logB + (size_t)b * TT * SS + j;

    // Y state: near-dot coefficients d=1..16 in registers (static params).
    float eDreg[16];
    float vh[15];
#pragma unroll
    for (int k = 0; k < 15; ++k) vh[k] = 0.0f;
    float w = 1.0f, rw = 1.0f;
    float frw_f = 1.0f, fw_f = 1.0f, fw_pend = 1.0f;
    float Cacc = 0.0f, lb0 = 0.0f, lb1 = 0.0f, vpi = 0.0f;
    if (isY) {
#pragma unroll
        for (int d = 0; d < 16; ++d) eDreg[d] = g_expD[d * SS + j];
        lb0 = lbp[0];
        lb1 = lbp[SS];
        rw  = ex2f(lb0 * LOG2E);
        vpi = g_vpi[j];
    }

    CARRIVE();                              // init done

    for (int kb = 0; kb < NBLK; ++kb) {
        CWAIT();                            // peer block-(kb-1) writes visible
        float fcor = 1.0f;
        const bool resc = (kb > 0) && ((kb & 3) == 0);
        if (resc) {
            if (!isC) {
                // local ring max scan: 2 half-ring rows per thread set
                const int cq = tid >> 7;    // 0..1
                float mxr = 0.0f;
#pragma unroll 4
                for (int s = 0; s < 64; ++s)
                    mxr = fmaxf(mxr, ring[(64 * cq + s) * SS + j]);
                pmax[cq * SS + j] = mxr;
                asm volatile("bar.sync 0;" ::: "memory");
                if (isY) {
                    float mv = fmaxf(pmax[j], pmax[SS + j]);
                    int e = 0;
                    if (mv > 0.0f) e = (__float_as_int(mv) >> 23) - 127;
                    float rsv  = __int_as_float((127 - e) << 23);  // 2^{-e}
                    float rsiv = __int_as_float((127 + e) << 23);  // 2^{+e}
                    rs[j] = rsv;
                    st_rm_f32(rs_rm + 4u * j, rsv);    // publish to conv CTA
                    w  *= rsv;
                    rw *= rsiv;
#pragma unroll
                    for (int k = 0; k < 15; ++k) vh[k] *= rsv;
                    fcor = rsv;    // deep sums were computed pre-rescale
                }
            }
            CARRIVE(); CWAIT();             // rs visible cluster-wide
            if (!isC) {
                float f = rs[j];
                const int cq = tid >> 7;
#pragma unroll 4
                for (int s = 0; s < 64; ++s)
                    ring[(64 * cq + s) * SS + j] *= f;
                asm volatile("bar.sync 0;" ::: "memory");
            } else {
                // rescale local replica, skipping the 8 slots Y overwrites
                // this block (dead slots — outside conv's read window).
                const int s0 = (8 * kb) & 127;
                for (int k = tid; k < 16384; k += NTHR) {
                    int slot = k >> 7;
                    if ((((slot - s0) & 127) >= 8))
                        ring[k] *= rs[k & 127];
                }
                asm volatile("bar.sync 0;" ::: "memory");
            }
        }

        if (!isC) {
            // Y: preload this block's deep sums (remote-written by conv)
            float deepR[8];
            if (isY) {
                const int buf = kb & 1;
#pragma unroll
                for (int tau = 0; tau < 8; ++tau) {
                    const float* dfb = dfar + ((buf * 4) * 8 + tau) * SS + j;
                    deepR[tau] = ((dfb[0] + dfb[8 * SS]) +
                                  (dfb[16 * SS] + dfb[24 * SS])) * fcor;
                }
            }
#pragma unroll
            for (int tau = 0; tau < 8; ++tau) {
                const int t = 8 * kb + tau;

                // ---- X: matvec partial over own 64-state band ----
                float tsum;
                {
                    const float4* p4 = (const float4*)psh;
                    const int base = isY ? 0 : 16;
                    ull s0 = 0ull, s1 = 0ull, s2 = 0ull, s3 = 0ull;
#pragma unroll
                    for (int kk = 0; kk < 16; kk += 2) {
                        float4 v0 = p4[base + kk];
                        float4 v1 = p4[base + kk + 1];
                        ffma2(s0, packf2(v0.x, v0.y), P[2 * kk]);
                        ffma2(s1, packf2(v0.z, v0.w), P[2 * kk + 1]);
                        ffma2(s2, packf2(v1.x, v1.y), P[2 * kk + 2]);
                        ffma2(s3, packf2(v1.z, v1.w), P[2 * kk + 3]);
                    }
                    float a2, b2, c2, d2, e2, f2, g2, h2;
                    unpackf2(s0, a2, b2); unpackf2(s1, c2, d2);
                    unpackf2(s2, e2, f2); unpackf2(s3, g2, h2);
                    tsum = ((a2 + b2) + (c2 + d2)) + ((e2 + f2) + (g2 + h2));
                }
                if (!isY) tp[j] = tsum;
                asm volatile("bar.sync 0;" ::: "memory");       // bar A

                // ---- Y: serial recurrence (register-only near-dot) ----
                if (isY) {
                    // off-chain: prefetch + scale-factor ex2's
                    float lbn = lbp[(size_t)min(t + 2, TT - 1) * SS];
                    float e2v = ex2f(lb1 * LOG2E);     // 2^{lb_{t+1}}
                    float ebv = ex2f(-lb0 * LOG2E);    // 2^{-lb_t}

                    float ts = tsum + tp[j];
                    float v  = (t == 0) ? vpi : ts * w;
                    ring[(t & 127) * SS + j] = v;               // local (pmax)
                    st_rm_f32(ring_rm + 4u * ((t & 127) * SS + j), v);  // conv

                    // near dot d=1..16, all-register FMAs
                    float n0 = v     * eDreg[0];
                    float n1 = vh[0] * eDreg[1];
                    float n2 = vh[1] * eDreg[2];
                    float n3 = vh[2] * eDreg[3];
#pragma unroll
                    for (int d2 = 4; d2 < 16; d2 += 4) {
                        n0 = fmaf(vh[d2 - 1], eDreg[d2    ], n0);
                        n1 = fmaf(vh[d2    ], eDreg[d2 + 1], n1);
                        n2 = fmaf(vh[d2 + 1], eDreg[d2 + 2], n2);
                        n3 = fmaf(vh[d2 + 2], eDreg[d2 + 3], n3);
                    }
                    float dot = ((n0 + n1) + (n2 + n3)) + deepR[tau];
                    float p = dot * rw;
                    psh[j] = p;

#pragma unroll
                    for (int k = 14; k > 0; --k) vh[k] = vh[k - 1];
                    vh[0] = v;

                    // psh renorm every 16 steps (exact power-of-2 factors)
                    if (tau == 7 && (kb & 1) == 1 && kb != NBLK - 1) {
                        unsigned um = __reduce_max_sync(0xffffffffu,
                                                        __float_as_uint(p));
                        if (lane == 0) wred[wrp] = __uint_as_float(um);
                        asm volatile("bar.sync 1, 128;" ::: "memory");
                        float mx = fmaxf(fmaxf(wred[0], wred[1]),
                                         fmaxf(wred[2], wred[3]));
                        int de = (__float_as_int(mx) >> 23) - 127;
                        Cacc += (float)de;
                        frw_f   = __int_as_float((127 - de) << 23);
                        fw_pend = __int_as_float((127 + de) << 23);
                    }

                    rw = rw * e2v * frw_f;  frw_f = 1.0f;
                    w  = w  * ebv * fw_f;   fw_f = fw_pend; fw_pend = 1.0f;
                    lb0 = lb1; lb1 = lbn;
                }
                asm volatile("bar.sync 0;" ::: "memory");       // bar B
            }
        } else {
            // ---- Conv CTA: deep duration sums (d=17..128) for block kb+1 ----
            const int t0 = 8 * (kb + 1);
            const int d0 = 17 + 28 * cb;
            const int u0 = t0 - d0 - 26;
            ull acc[8] = {0ull,0ull,0ull,0ull,0ull,0ull,0ull,0ull};
#pragma unroll
            for (int m = 0; m < 35; ++m) {
                ull v = *(const ull*)&ring[((u0 + m + 8192) & 127) * SS + 2 * cp];
#pragma unroll
                for (int tau = 0; tau < 8; ++tau) {
                    int q = tau + 27 - m;
                    if (q >= 0 && q <= 27) ffma2(acc[tau], v, P[q]);
                }
            }
            const int obuf = (kb + 1) & 1;
            unsigned dst = df_rm + 4u * (((obuf * 4 + cb) * 8) * SS + 2 * cp);
#pragma unroll
            for (int tau = 0; tau < 8; ++tau)
                st_rm_u64(dst + 4u * (tau * SS), acc[tau]);
        }
        CARRIVE();                          // my block-kb writes published
    }

    CWAIT();                                // balance final arrive

    // loglik[b] = ln2 * (Cacc + lg2(sum_j psh_j))  — rank 0 only
    if (isY) {
        float s = psh[j];
#pragma unroll
        for (int o = 16; o; o >>= 1)
            s += __shfl_xor_sync(0xffffffffu, s, o);
        if (lane == 0) wred[wrp] = s;
        asm volatile("bar.sync 1, 128;" ::: "memory");
        if (tid == 0) {
            float tot = (wred[0] + wred[1]) + (wred[2] + wred[3]);
            out[b] = (Cacc + lg2f(tot)) * LN2F;
        }
    }
}

extern "C" void kernel_launch(void* const* d_in, const int* in_sizes, int n_in,
                              void* d_out, int out_size) {
    const float* logB = (const float*)d_in[0];  // (B, T, S)
    const float* pi   = (const float*)d_in[1];  // (S,)
    const float* A    = (const float*)d_in[2];  // (S, S)
    const float* D    = (const float*)d_in[3];  // (S, DMAX)

    hsmm_precompute<<<128, 128>>>(A, D, pi);

    cudaFuncSetAttribute(hsmm_kernel,
                         cudaFuncAttributeMaxDynamicSharedMemorySize, SMEM_BYTES);
    hsmm_kernel<<<2 * BB, NTHR, SMEM_BYTES>>>(logB, (float*)d_out);
}